// round 14
// baseline (speedup 1.0000x reference)
#include <cuda_runtime.h>
#include <cuda_bf16.h>

#define HEADS 4
#define CHEAD 32
#define CIN   256
#define CHID  128
#define NTOK  4096
#define BATCH 4
#define BH    (BATCH * HEADS)

#define QSCALE ((float)(0.17677669529663687 * 1.4426950408889634))
#define FIXMAX 16.0f
#define LINV   0.03125f      /* 1/32 */

// ---------------- device scratch (P0 / P1 fp16-pair arrays) ----------------
__device__ unsigned g_xhi[BATCH * CIN * NTOK / 2];
__device__ unsigned g_xlo[BATCH * CIN * NTOK / 2];
__device__ unsigned g_wqhi[384 * 256 / 2];
__device__ unsigned g_wqlo[384 * 256 / 2];
__device__ unsigned g_wohi[256 * 128 / 2];
__device__ unsigned g_wolo[256 * 128 / 2];
__device__ uint4 g_qhi[BH * NTOK * 4];
__device__ uint4 g_qlo[BH * NTOK * 4];
__device__ uint4 g_khi[BH * NTOK * 4];
__device__ uint4 g_klo[BH * NTOK * 4];
__device__ uint4 g_vhi[BH * NTOK * 4];
__device__ uint4 g_vlo[BH * NTOK * 4];
__device__ unsigned g_ahi[BATCH * NTOK * 64];
__device__ unsigned g_alo[BATCH * NTOK * 64];

// ---------------- helpers ----------------
__device__ __forceinline__ unsigned s2u(const void* p) {
    unsigned r;
    asm("{.reg .u64 t; cvta.to.shared.u64 t,%1; cvt.u32.u64 %0,t;}" : "=r"(r) : "l"(p));
    return r;
}
__device__ __forceinline__ float ex2f(float x) {
    float y; asm("ex2.approx.f32 %0,%1;" : "=f"(y) : "f"(x)); return y;
}
// fp16 lambda-split (lambda=32): P0 = fp16(x); P1 = fp16(P0 + 32*(x-P0)).
// Reconstruct: x*y ~= (31/32)*P0a*P0b + (1/32)*P1a*P1b  (err ~2e-5)
__device__ __forceinline__ void splitH(float a, float b, unsigned& p0, unsigned& p1) {
    unsigned h;
    asm("cvt.rn.f16x2.f32 %0,%1,%2;" : "=r"(h) : "f"(b), "f"(a));   // lo=a, hi=b
    float ha, hb;
    asm("{.reg .f16 x,y; mov.b32 {x,y},%2; cvt.f32.f16 %0,x; cvt.f32.f16 %1,y;}"
        : "=f"(ha), "=f"(hb) : "r"(h));
    float pa = fmaf(a - ha, 32.f, ha);
    float pb = fmaf(b - hb, 32.f, hb);
    asm("cvt.rn.f16x2.f32 %0,%1,%2;" : "=r"(p1) : "f"(pb), "f"(pa));
    p0 = h;
}
__device__ __forceinline__ float lcomb(float d1, float d2) {
    return fmaf(d2 - d1, LINV, d1);     // (31/32)d1 + (1/32)d2
}

#define MMA_F16(d, a0, a1, a2, a3, b0, b1) \
    asm volatile("mma.sync.aligned.m16n8k16.row.col.f32.f16.f16.f32 " \
        "{%0,%1,%2,%3},{%4,%5,%6,%7},{%8,%9},{%0,%1,%2,%3};" \
        : "+f"((d)[0]), "+f"((d)[1]), "+f"((d)[2]), "+f"((d)[3]) \
        : "r"(a0), "r"(a1), "r"(a2), "r"(a3), "r"(b0), "r"(b1))

#define LDSM_X4(r0, r1, r2, r3, a) \
    asm volatile("ldmatrix.sync.aligned.m8n8.x4.shared.b16 {%0,%1,%2,%3},[%4];" \
        : "=r"(r0), "=r"(r1), "=r"(r2), "=r"(r3) : "r"(a))
#define LDSM_X4_T(r0, r1, r2, r3, a) \
    asm volatile("ldmatrix.sync.aligned.m8n8.x4.trans.shared.b16 {%0,%1,%2,%3},[%4];" \
        : "=r"(r0), "=r"(r1), "=r"(r2), "=r"(r3) : "r"(a))

#define CP_ASYNC(dst, src) \
    asm volatile("cp.async.cg.shared.global [%0],[%1],16;" :: "r"(dst), "l"(src))
#define CP_COMMIT() asm volatile("cp.async.commit_group;")
#define CP_WAIT(n)  asm volatile("cp.async.wait_group %0;" :: "n"(n) : "memory")

// ============================================================================
// Kernel 0: split x / w_qkv / w_out into fp16 P0/P1 pairs
// ============================================================================
#define NX2  (BATCH * CIN * NTOK / 2)
#define NWQ2 (384 * 256 / 2)
#define NWO2 (256 * 128 / 2)

__global__ __launch_bounds__(256) void split_kernel(const float* __restrict__ x,
                                                    const float* __restrict__ wq,
                                                    const float* __restrict__ wo)
{
    int i = blockIdx.x * 256 + threadIdx.x;
    if (i >= NX2 + NWQ2 + NWO2) return;
    const float2* src; unsigned *dh, *dl; int j;
    if (i < NX2)              { j = i;               src = (const float2*)x;  dh = g_xhi;  dl = g_xlo; }
    else if (i < NX2 + NWQ2)  { j = i - NX2;         src = (const float2*)wq; dh = g_wqhi; dl = g_wqlo; }
    else                      { j = i - NX2 - NWQ2;  src = (const float2*)wo; dh = g_wohi; dl = g_wolo; }
    float2 v = src[j];
    unsigned h, l; splitH(v.x, v.y, h, l);
    dh[j] = h; dl[j] = l;
}

// ============================================================================
// Kernel 1: QKV projection, HMMA fp16 lambda-split (4 MMAs per frag pair)
// ============================================================================
#define QX_ROW 272
#define QXL    8704
#define QWH    17408
#define QW_ROW 80
#define QBUF   27648

__global__ __launch_bounds__(256) void qkv_mma()
{
    extern __shared__ unsigned char qs[];
    unsigned sb = s2u(qs);
    int tid = threadIdx.x, lane = tid & 31, wid = tid >> 5;
    int lrow = lane & 7, lmi = lane >> 3;
    int g = lane >> 2, tq = lane & 3;
    int n0 = blockIdx.x * 128, o0 = blockIdx.y * 64, b = blockIdx.z;

    float s1[8][4], s2[8][4];
    #pragma unroll
    for (int i = 0; i < 8; i++)
        #pragma unroll
        for (int j = 0; j < 4; j++) { s1[i][j] = 0.f; s2[i][j] = 0.f; }

    auto load_slice = [&](int ks, int buf) {
        unsigned bb = sb + buf * QBUF;
        #pragma unroll
        for (int i = tid; i < 1024; i += 256) {
            int arr = i >> 9, ch = i & 511, c = ch >> 4, c16 = ch & 15;
            unsigned dst = bb + arr * QXL + c * QX_ROW + c16 * 16;
            const char* src = (const char*)(arr ? g_xlo : g_xhi)
                + (((size_t)(b * CIN + ks * 32 + c)) * 2048 + (n0 >> 1) + c16 * 4) * 4;
            CP_ASYNC(dst, src);
        }
        #pragma unroll
        for (int i = tid; i < 512; i += 256) {
            int arr = i >> 8, ch = i & 255, o = ch >> 2, c16 = ch & 3;
            unsigned dst = bb + QWH + arr * 5120 + o * QW_ROW + c16 * 16;
            const char* src = (const char*)(arr ? g_wqlo : g_wqhi)
                + (((size_t)(o0 + o)) * 128 + ks * 16 + c16 * 4) * 4;
            CP_ASYNC(dst, src);
        }
        CP_COMMIT();
    };

    load_slice(0, 0);
    for (int ks = 0; ks < 8; ks++) {
        if (ks < 7) { load_slice(ks + 1, (ks + 1) & 1); CP_WAIT(1); }
        else        { CP_WAIT(0); }
        __syncthreads();

        unsigned xb = sb + (ks & 1) * QBUF;
        unsigned wb = xb + QWH;

        unsigned abase = xb + ((unsigned)((lane >> 4) * 8 + lrow)) * QX_ROW
                       + (wid * 16 + ((lane >> 3) & 1) * 8) * 2;
        unsigned ax00[4], ax01[4], ax10[4], ax11[4];
        LDSM_X4_T(ax00[0], ax00[1], ax00[2], ax00[3], abase);                      // P0, kc0
        LDSM_X4_T(ax01[0], ax01[1], ax01[2], ax01[3], abase + 16 * QX_ROW);        // P0, kc1
        LDSM_X4_T(ax10[0], ax10[1], ax10[2], ax10[3], abase + QXL);                // P1, kc0
        LDSM_X4_T(ax11[0], ax11[1], ax11[2], ax11[3], abase + QXL + 16 * QX_ROW);  // P1, kc1

        unsigned bbase = wb + lrow * QW_ROW + lmi * 16;
        #pragma unroll
        for (int ot = 0; ot < 8; ot++) {
            unsigned bh0, bh1, bh2, bh3, bl0, bl1, bl2, bl3;
            unsigned ba = bbase + ot * (8 * QW_ROW);
            LDSM_X4(bh0, bh1, bh2, bh3, ba);
            LDSM_X4(bl0, bl1, bl2, bl3, ba + 5120);
            MMA_F16(s1[ot], ax00[0], ax00[1], ax00[2], ax00[3], bh0, bh1);
            MMA_F16(s1[ot], ax01[0], ax01[1], ax01[2], ax01[3], bh2, bh3);
            MMA_F16(s2[ot], ax10[0], ax10[1], ax10[2], ax10[3], bl0, bl1);
            MMA_F16(s2[ot], ax11[0], ax11[1], ax11[2], ax11[3], bl2, bl3);
        }
        __syncthreads();
    }

    int nr = n0 + wid * 16 + g;
    #pragma unroll
    for (int ot = 0; ot < 8; ot++) {
        int o = o0 + ot * 8 + 2 * tq;
        int kind = o >> 7, hh = (o >> 5) & 3, c = o & 31;
        unsigned* dh = (unsigned*)(kind == 0 ? g_qhi : (kind == 1 ? g_khi : g_vhi));
        unsigned* dl = (unsigned*)(kind == 0 ? g_qlo : (kind == 1 ? g_klo : g_vlo));
        float sc = (kind == 0) ? QSCALE : 1.f;
        size_t i0 = ((size_t)(b * HEADS + hh) * NTOK + nr) * 16 + (c >> 1);
        unsigned h0, l0;
        splitH(lcomb(s1[ot][0], s2[ot][0]) * sc, lcomb(s1[ot][1], s2[ot][1]) * sc, h0, l0);
        dh[i0] = h0; dl[i0] = l0;
        splitH(lcomb(s1[ot][2], s2[ot][2]) * sc, lcomb(s1[ot][3], s2[ot][3]) * sc, h0, l0);
        dh[i0 + 128] = h0; dl[i0 + 128] = l0;
    }
}

// ============================================================================
// Kernel 2: FlashAttention, fp16 lambda-split (2 MMAs per GEMM term).
// 16q/warp, 64q/128thr CTA; 64-key tiles double-buffered; fixed-max softmax.
// ============================================================================
#define ROWB 80
#define ARRB (64 * ROWB)        // 5120
#define BUFB (4 * ARRB)         // 20480; 2 buffers = 40KB static

struct __align__(16) FSmem { unsigned char kv[2][4][ARRB]; };

__global__ __launch_bounds__(128) void fattn_kernel()
{
    __shared__ FSmem fs;
    unsigned sb = s2u(&fs);
    int tid = threadIdx.x;
    int lane = tid & 31, wid = tid >> 5;
    int qt = blockIdx.x, bh = blockIdx.y;
    int g = lane >> 2, tq = lane & 3;
    int lrow = lane & 7, lmi = lane >> 3;

    const uint4* srcs[4] = {
        g_khi + (size_t)bh * NTOK * 4, g_klo + (size_t)bh * NTOK * 4,
        g_vhi + (size_t)bh * NTOK * 4, g_vlo + (size_t)bh * NTOK * 4 };

    int c16 = tid & 3, r0 = tid >> 2;
    {
        #pragma unroll
        for (int i = 0; i < 8; i++) {
            int arr = i >> 1, row = (r0 + i * 32) & 63;
            unsigned dst = sb + arr * ARRB + row * ROWB + c16 * 16;
            CP_ASYNC(dst, srcs[arr] + (size_t)row * 4 + c16);
        }
        CP_COMMIT();
    }

    // ---- Q fragments (P0 / P1), 2 k-chunks ----
    unsigned q0[2][4], q1[2][4];
    {
        int qa = qt * 64 + wid * 16 + g;
        const unsigned* ph = (const unsigned*)(g_qhi + ((size_t)bh * NTOK + qa) * 4);
        const unsigned* pl = (const unsigned*)(g_qlo + ((size_t)bh * NTOK + qa) * 4);
        #pragma unroll
        for (int kb = 0; kb < 2; kb++) {
            q0[kb][0] = ph[8 * kb + tq];       q0[kb][2] = ph[8 * kb + 4 + tq];
            q0[kb][1] = ph[128 + 8 * kb + tq]; q0[kb][3] = ph[128 + 8 * kb + 4 + tq];
            q1[kb][0] = pl[8 * kb + tq];       q1[kb][2] = pl[8 * kb + 4 + tq];
            q1[kb][1] = pl[128 + 8 * kb + tq]; q1[kb][3] = pl[128 + 8 * kb + 4 + tq];
        }
    }

    float o1[4][4], o2[4][4];
    #pragma unroll
    for (int i = 0; i < 4; i++)
        #pragma unroll
        for (int j = 0; j < 4; j++) { o1[i][j] = 0.f; o2[i][j] = 0.f; }
    float l_a = 0.f, l_b = 0.f;

    int buf = 0;
    for (int kt = 0; kt < NTOK / 64; kt++) {
        if (kt < NTOK / 64 - 1) {
            unsigned bb = sb + (buf ^ 1) * BUFB;
            size_t goff = (size_t)(kt + 1) * 64 * 4;
            #pragma unroll
            for (int i = 0; i < 8; i++) {
                int arr = i >> 1, row = (r0 + i * 32) & 63;
                CP_ASYNC(bb + arr * ARRB + row * ROWB + c16 * 16,
                         srcs[arr] + goff + (size_t)row * 4 + c16);
            }
            CP_COMMIT();
            CP_WAIT(1);
        } else {
            CP_WAIT(0);
        }
        __syncthreads();

        unsigned kb_base = sb + buf * BUFB;

        // ---- S = lambda-combined Q.K^T : 4 MMAs per 8-key block ----
        float s1[8][4], s2[8][4];
        #pragma unroll
        for (int nb = 0; nb < 8; nb++)
            #pragma unroll
            for (int i = 0; i < 4; i++) { s1[nb][i] = 0.f; s2[nb][i] = 0.f; }

        #pragma unroll
        for (int nb = 0; nb < 8; nb++) {
            unsigned k00, k01, k02, k03, k10, k11, k12, k13;
            unsigned ka = kb_base + (8 * nb + lrow) * ROWB + lmi * 16;
            LDSM_X4(k00, k01, k02, k03, ka);
            LDSM_X4(k10, k11, k12, k13, ka + ARRB);
            MMA_F16(s1[nb], q0[0][0], q0[0][1], q0[0][2], q0[0][3], k00, k01);
            MMA_F16(s1[nb], q0[1][0], q0[1][1], q0[1][2], q0[1][3], k02, k03);
            MMA_F16(s2[nb], q1[0][0], q1[0][1], q1[0][2], q1[0][3], k10, k11);
            MMA_F16(s2[nb], q1[1][0], q1[1][1], q1[1][2], q1[1][3], k12, k13);
        }

        // ---- combine + fixed-max softmax ----
        float sa = 0.f, sbm = 0.f;
        #pragma unroll
        for (int nb = 0; nb < 8; nb++) {
            s1[nb][0] = ex2f(lcomb(s1[nb][0], s2[nb][0]) - FIXMAX);
            s1[nb][1] = ex2f(lcomb(s1[nb][1], s2[nb][1]) - FIXMAX);
            s1[nb][2] = ex2f(lcomb(s1[nb][2], s2[nb][2]) - FIXMAX);
            s1[nb][3] = ex2f(lcomb(s1[nb][3], s2[nb][3]) - FIXMAX);
            sa  += s1[nb][0] + s1[nb][1];
            sbm += s1[nb][2] + s1[nb][3];
        }
        l_a += sa; l_b += sbm;

        // ---- O (lambda-split P and V): 4 MMAs per (kb,cp) ----
        unsigned vbase = kb_base + 2 * ARRB;
        #pragma unroll
        for (int kb = 0; kb < 4; kb++) {
            unsigned p0[4], p1[4];
            splitH(s1[2 * kb][0],     s1[2 * kb][1],     p0[0], p1[0]);
            splitH(s1[2 * kb][2],     s1[2 * kb][3],     p0[1], p1[1]);
            splitH(s1[2 * kb + 1][0], s1[2 * kb + 1][1], p0[2], p1[2]);
            splitH(s1[2 * kb + 1][2], s1[2 * kb + 1][3], p0[3], p1[3]);
            #pragma unroll
            for (int cp = 0; cp < 2; cp++) {
                int oct = 2 * kb + (lmi & 1), chunk = 2 * cp + (lmi >> 1);
                unsigned va = vbase + (oct * 8 + lrow) * ROWB + chunk * 16;
                unsigned v00, v01, v02, v03, v10, v11, v12, v13;
                LDSM_X4_T(v00, v01, v02, v03, va);
                LDSM_X4_T(v10, v11, v12, v13, va + ARRB);
                MMA_F16(o1[2 * cp],     p0[0], p0[1], p0[2], p0[3], v00, v01);
                MMA_F16(o1[2 * cp + 1], p0[0], p0[1], p0[2], p0[3], v02, v03);
                MMA_F16(o2[2 * cp],     p1[0], p1[1], p1[2], p1[3], v10, v11);
                MMA_F16(o2[2 * cp + 1], p1[0], p1[1], p1[2], p1[3], v12, v13);
            }
        }

        __syncthreads();
        buf ^= 1;
    }

    // ---- l reductions ----
    l_a += __shfl_xor_sync(0xffffffffu, l_a, 1);
    l_a += __shfl_xor_sync(0xffffffffu, l_a, 2);
    l_b += __shfl_xor_sync(0xffffffffu, l_b, 1);
    l_b += __shfl_xor_sync(0xffffffffu, l_b, 2);

    // ---- epilogue: lambda-combine O, normalize, split to P0/P1 ----
    float inv_a = 1.f / l_a, inv_b = 1.f / l_b;
    int b = bh >> 2, h = bh & 3;
    int qa = qt * 64 + wid * 16 + g;
    #pragma unroll
    for (int nb = 0; nb < 4; nb++) {
        int c = h * 32 + nb * 8 + 2 * tq;
        size_t i0 = ((size_t)b * NTOK + qa) * 64 + (c >> 1);
        unsigned hA, lA;
        splitH(lcomb(o1[nb][0], o2[nb][0]) * inv_a,
               lcomb(o1[nb][1], o2[nb][1]) * inv_a, hA, lA);
        g_ahi[i0] = hA; g_alo[i0] = lA;
        splitH(lcomb(o1[nb][2], o2[nb][2]) * inv_b,
               lcomb(o1[nb][3], o2[nb][3]) * inv_b, hA, lA);
        g_ahi[i0 + 8 * 64] = hA; g_alo[i0 + 8 * 64] = lA;
    }
}

// ============================================================================
// Kernel 3: output projection, fp16 lambda-split (4 MMAs per frag pair)
// ============================================================================
#define OROW 272
#define OARR 17408

__global__ __launch_bounds__(256) void out_mma(const float* __restrict__ bias,
                                               float* __restrict__ out)
{
    extern __shared__ unsigned char osm[];
    unsigned sb = s2u(osm);
    int tid = threadIdx.x, lane = tid & 31, wid = tid >> 5;
    int lrow = lane & 7, lmi = lane >> 3;
    int g = lane >> 2, tq = lane & 3;
    int n0 = blockIdx.x * 64, o0 = blockIdx.y * 64, b = blockIdx.z;

    #pragma unroll
    for (int i = tid; i < 4096; i += 256) {
        int arr = i >> 10, ch = i & 1023, r = ch >> 4, c16 = ch & 15;
        unsigned dst = sb + arr * OARR + r * OROW + c16 * 16;
        const char* src;
        if (arr < 2)
            src = (const char*)(arr ? g_wolo : g_wohi)
                + (((size_t)(o0 + r)) * 64 + c16 * 4) * 4;
        else
            src = (const char*)(arr == 2 ? g_ahi : g_alo)
                + (((size_t)(b * NTOK + n0 + r)) * 64 + c16 * 4) * 4;
        CP_ASYNC(dst, src);
    }
    CP_COMMIT(); CP_WAIT(0);
    __syncthreads();

    int ow = wid >> 1, nh = wid & 1;
    float s1[4][4], s2[4][4];
    #pragma unroll
    for (int i = 0; i < 4; i++)
        #pragma unroll
        for (int j = 0; j < 4; j++) { s1[i][j] = 0.f; s2[i][j] = 0.f; }

    unsigned abase = sb + (ow * 16 + (lane & 15)) * OROW + (lane >> 4) * 16;
    unsigned bbase = sb + 2 * OARR + (nh * 32 + lrow) * OROW + lmi * 16;

    #pragma unroll
    for (int ksl = 0; ksl < 4; ksl++) {
        unsigned ax00[4], ax01[4], ax10[4], ax11[4];
        LDSM_X4(ax00[0], ax00[1], ax00[2], ax00[3], abase + ksl * 64);
        LDSM_X4(ax01[0], ax01[1], ax01[2], ax01[3], abase + ksl * 64 + 32);
        LDSM_X4(ax10[0], ax10[1], ax10[2], ax10[3], abase + OARR + ksl * 64);
        LDSM_X4(ax11[0], ax11[1], ax11[2], ax11[3], abase + OARR + ksl * 64 + 32);
        #pragma unroll
        for (int nt = 0; nt < 4; nt++) {
            unsigned bh0, bh1, bh2, bh3, bl0, bl1, bl2, bl3;
            unsigned ba = bbase + nt * (8 * OROW) + ksl * 64;
            LDSM_X4(bh0, bh1, bh2, bh3, ba);
            LDSM_X4(bl0, bl1, bl2, bl3, ba + OARR);
            MMA_F16(s1[nt], ax00[0], ax00[1], ax00[2], ax00[3], bh0, bh1);
            MMA_F16(s1[nt], ax01[0], ax01[1], ax01[2], ax01[3], bh2, bh3);
            MMA_F16(s2[nt], ax10[0], ax10[1], ax10[2], ax10[3], bl0, bl1);
            MMA_F16(s2[nt], ax11[0], ax11[1], ax11[2], ax11[3], bl2, bl3);
        }
    }

    int o = o0 + ow * 16 + g;
    float b0 = bias[o], b1 = bias[o + 8];
    #pragma unroll
    for (int nt = 0; nt < 4; nt++) {
        int n = n0 + nh * 32 + nt * 8 + 2 * tq;
        *(float2*)&out[((size_t)(b * CIN + o)) * NTOK + n] =
            make_float2(lcomb(s1[nt][0], s2[nt][0]) + b0,
                        lcomb(s1[nt][1], s2[nt][1]) + b0);
        *(float2*)&out[((size_t)(b * CIN + o + 8)) * NTOK + n] =
            make_float2(lcomb(s1[nt][2], s2[nt][2]) + b1,
                        lcomb(s1[nt][3], s2[nt][3]) + b1);
    }
}

// ============================================================================
extern "C" void kernel_launch(void* const* d_in, const int* in_sizes, int n_in,
                              void* d_out, int out_size)
{
    (void)in_sizes; (void)n_in; (void)out_size;
    const float* x     = (const float*)d_in[0];
    const float* w_qkv = (const float*)d_in[1];
    const float* w_out = (const float*)d_in[2];
    const float* b_out = (const float*)d_in[3];
    float* out = (float*)d_out;

    cudaFuncSetAttribute(qkv_mma, cudaFuncAttributeMaxDynamicSharedMemorySize, 2 * QBUF);
    cudaFuncSetAttribute(out_mma, cudaFuncAttributeMaxDynamicSharedMemorySize, 4 * OARR);

    int total = NX2 + NWQ2 + NWO2;
    split_kernel<<<(total + 255) / 256, 256>>>(x, w_qkv, w_out);
    qkv_mma<<<dim3(32, 6, 4), 256, 2 * QBUF>>>();
    fattn_kernel<<<dim3(NTOK / 64, BH), 128>>>();
    out_mma<<<dim3(64, 4, 4), 256, 4 * OARR>>>(b_out, out);
}

// round 15
// speedup vs baseline: 1.4580x; 1.4580x over previous
#include <cuda_runtime.h>
#include <cuda_bf16.h>

#define HEADS 4
#define CHEAD 32
#define CIN   256
#define CHID  128
#define NTOK  4096
#define BATCH 4
#define BH    (BATCH * HEADS)

#define QSCALE ((float)(0.17677669529663687 * 1.4426950408889634))
#define FIXMAX 16.0f
#define LINV   0.03125f      /* 1/32 */

// ---------------- device scratch (P0 / P1 bf16-lambda-pair arrays) ----------
__device__ unsigned g_xhi[BATCH * CIN * NTOK / 2];
__device__ unsigned g_xlo[BATCH * CIN * NTOK / 2];
__device__ unsigned g_wqhi[384 * 256 / 2];
__device__ unsigned g_wqlo[384 * 256 / 2];
__device__ unsigned g_wohi[256 * 128 / 2];
__device__ unsigned g_wolo[256 * 128 / 2];
__device__ uint4 g_qhi[BH * NTOK * 4];
__device__ uint4 g_qlo[BH * NTOK * 4];
__device__ uint4 g_khi[BH * NTOK * 4];
__device__ uint4 g_klo[BH * NTOK * 4];
__device__ uint4 g_vhi[BH * NTOK * 4];
__device__ uint4 g_vlo[BH * NTOK * 4];
__device__ unsigned g_ahi[BATCH * NTOK * 64];
__device__ unsigned g_alo[BATCH * NTOK * 64];

// ---------------- helpers ----------------
__device__ __forceinline__ unsigned s2u(const void* p) {
    unsigned r;
    asm("{.reg .u64 t; cvta.to.shared.u64 t,%1; cvt.u32.u64 %0,t;}" : "=r"(r) : "l"(p));
    return r;
}
__device__ __forceinline__ float ex2f(float x) {
    float y; asm("ex2.approx.f32 %0,%1;" : "=f"(y) : "f"(x)); return y;
}
// bf16 lambda-split (lambda=32): P0 = bf16(x); P1 = bf16(P0 + 32*(x-P0)).
// Reconstruct: x*y ~= (31/32)*P0a*P0b + (1/32)*P1a*P1b  (err ~2.5e-4)
__device__ __forceinline__ void splitB(float a, float b, unsigned& p0, unsigned& p1) {
    unsigned h;
    asm("cvt.rn.bf16x2.f32 %0,%1,%2;" : "=r"(h) : "f"(b), "f"(a));   // lo=a, hi=b
    float ha = __uint_as_float(h << 16);
    float hb = __uint_as_float(h & 0xffff0000u);
    float pa = fmaf(a - ha, 32.f, ha);
    float pb = fmaf(b - hb, 32.f, hb);
    asm("cvt.rn.bf16x2.f32 %0,%1,%2;" : "=r"(p1) : "f"(pb), "f"(pa));
    p0 = h;
}
__device__ __forceinline__ float lcomb(float d1, float d2) {
    return fmaf(d2 - d1, LINV, d1);     // (31/32)d1 + (1/32)d2
}

#define MMA_BF16(d, a0, a1, a2, a3, b0, b1) \
    asm volatile("mma.sync.aligned.m16n8k16.row.col.f32.bf16.bf16.f32 " \
        "{%0,%1,%2,%3},{%4,%5,%6,%7},{%8,%9},{%0,%1,%2,%3};" \
        : "+f"((d)[0]), "+f"((d)[1]), "+f"((d)[2]), "+f"((d)[3]) \
        : "r"(a0), "r"(a1), "r"(a2), "r"(a3), "r"(b0), "r"(b1))

#define LDSM_X4(r0, r1, r2, r3, a) \
    asm volatile("ldmatrix.sync.aligned.m8n8.x4.shared.b16 {%0,%1,%2,%3},[%4];" \
        : "=r"(r0), "=r"(r1), "=r"(r2), "=r"(r3) : "r"(a))
#define LDSM_X4_T(r0, r1, r2, r3, a) \
    asm volatile("ldmatrix.sync.aligned.m8n8.x4.trans.shared.b16 {%0,%1,%2,%3},[%4];" \
        : "=r"(r0), "=r"(r1), "=r"(r2), "=r"(r3) : "r"(a))

#define CP_ASYNC(dst, src) \
    asm volatile("cp.async.cg.shared.global [%0],[%1],16;" :: "r"(dst), "l"(src))
#define CP_COMMIT() asm volatile("cp.async.commit_group;")
#define CP_WAIT(n)  asm volatile("cp.async.wait_group %0;" :: "n"(n) : "memory")

// ============================================================================
// Kernel 0: split x / w_qkv / w_out into bf16 lambda pairs
// ============================================================================
#define NX2  (BATCH * CIN * NTOK / 2)
#define NWQ2 (384 * 256 / 2)
#define NWO2 (256 * 128 / 2)

__global__ __launch_bounds__(256) void split_kernel(const float* __restrict__ x,
                                                    const float* __restrict__ wq,
                                                    const float* __restrict__ wo)
{
    int i = blockIdx.x * 256 + threadIdx.x;
    if (i >= NX2 + NWQ2 + NWO2) return;
    const float2* src; unsigned *dh, *dl; int j;
    if (i < NX2)              { j = i;               src = (const float2*)x;  dh = g_xhi;  dl = g_xlo; }
    else if (i < NX2 + NWQ2)  { j = i - NX2;         src = (const float2*)wq; dh = g_wqhi; dl = g_wqlo; }
    else                      { j = i - NX2 - NWQ2;  src = (const float2*)wo; dh = g_wohi; dl = g_wolo; }
    float2 v = src[j];
    unsigned h, l; splitB(v.x, v.y, h, l);
    dh[j] = h; dl[j] = l;
}

// ============================================================================
// Kernel 1: QKV projection, bf16 lambda-split (4 MMAs per frag pair)
// ============================================================================
#define QX_ROW 272
#define QXL    8704
#define QWH    17408
#define QW_ROW 80
#define QBUF   27648

__global__ __launch_bounds__(256) void qkv_mma()
{
    extern __shared__ unsigned char qs[];
    unsigned sb = s2u(qs);
    int tid = threadIdx.x, lane = tid & 31, wid = tid >> 5;
    int lrow = lane & 7, lmi = lane >> 3;
    int g = lane >> 2, tq = lane & 3;
    int n0 = blockIdx.x * 128, o0 = blockIdx.y * 64, b = blockIdx.z;

    float s1[8][4], s2[8][4];
    #pragma unroll
    for (int i = 0; i < 8; i++)
        #pragma unroll
        for (int j = 0; j < 4; j++) { s1[i][j] = 0.f; s2[i][j] = 0.f; }

    auto load_slice = [&](int ks, int buf) {
        unsigned bb = sb + buf * QBUF;
        #pragma unroll
        for (int i = tid; i < 1024; i += 256) {
            int arr = i >> 9, ch = i & 511, c = ch >> 4, c16 = ch & 15;
            unsigned dst = bb + arr * QXL + c * QX_ROW + c16 * 16;
            const char* src = (const char*)(arr ? g_xlo : g_xhi)
                + (((size_t)(b * CIN + ks * 32 + c)) * 2048 + (n0 >> 1) + c16 * 4) * 4;
            CP_ASYNC(dst, src);
        }
        #pragma unroll
        for (int i = tid; i < 512; i += 256) {
            int arr = i >> 8, ch = i & 255, o = ch >> 2, c16 = ch & 3;
            unsigned dst = bb + QWH + arr * 5120 + o * QW_ROW + c16 * 16;
            const char* src = (const char*)(arr ? g_wqlo : g_wqhi)
                + (((size_t)(o0 + o)) * 128 + ks * 16 + c16 * 4) * 4;
            CP_ASYNC(dst, src);
        }
        CP_COMMIT();
    };

    load_slice(0, 0);
    for (int ks = 0; ks < 8; ks++) {
        if (ks < 7) { load_slice(ks + 1, (ks + 1) & 1); CP_WAIT(1); }
        else        { CP_WAIT(0); }
        __syncthreads();

        unsigned xb = sb + (ks & 1) * QBUF;
        unsigned wb = xb + QWH;

        unsigned abase = xb + ((unsigned)((lane >> 4) * 8 + lrow)) * QX_ROW
                       + (wid * 16 + ((lane >> 3) & 1) * 8) * 2;
        unsigned ax00[4], ax01[4], ax10[4], ax11[4];
        LDSM_X4_T(ax00[0], ax00[1], ax00[2], ax00[3], abase);                      // P0, kc0
        LDSM_X4_T(ax01[0], ax01[1], ax01[2], ax01[3], abase + 16 * QX_ROW);        // P0, kc1
        LDSM_X4_T(ax10[0], ax10[1], ax10[2], ax10[3], abase + QXL);                // P1, kc0
        LDSM_X4_T(ax11[0], ax11[1], ax11[2], ax11[3], abase + QXL + 16 * QX_ROW);  // P1, kc1

        unsigned bbase = wb + lrow * QW_ROW + lmi * 16;
        #pragma unroll
        for (int ot = 0; ot < 8; ot++) {
            unsigned bh0, bh1, bh2, bh3, bl0, bl1, bl2, bl3;
            unsigned ba = bbase + ot * (8 * QW_ROW);
            LDSM_X4(bh0, bh1, bh2, bh3, ba);
            LDSM_X4(bl0, bl1, bl2, bl3, ba + 5120);
            MMA_BF16(s1[ot], ax00[0], ax00[1], ax00[2], ax00[3], bh0, bh1);
            MMA_BF16(s1[ot], ax01[0], ax01[1], ax01[2], ax01[3], bh2, bh3);
            MMA_BF16(s2[ot], ax10[0], ax10[1], ax10[2], ax10[3], bl0, bl1);
            MMA_BF16(s2[ot], ax11[0], ax11[1], ax11[2], ax11[3], bl2, bl3);
        }
        __syncthreads();
    }

    int nr = n0 + wid * 16 + g;
    #pragma unroll
    for (int ot = 0; ot < 8; ot++) {
        int o = o0 + ot * 8 + 2 * tq;
        int kind = o >> 7, hh = (o >> 5) & 3, c = o & 31;
        unsigned* dh = (unsigned*)(kind == 0 ? g_qhi : (kind == 1 ? g_khi : g_vhi));
        unsigned* dl = (unsigned*)(kind == 0 ? g_qlo : (kind == 1 ? g_klo : g_vlo));
        float sc = (kind == 0) ? QSCALE : 1.f;
        size_t i0 = ((size_t)(b * HEADS + hh) * NTOK + nr) * 16 + (c >> 1);
        unsigned h0, l0;
        splitB(lcomb(s1[ot][0], s2[ot][0]) * sc, lcomb(s1[ot][1], s2[ot][1]) * sc, h0, l0);
        dh[i0] = h0; dl[i0] = l0;
        splitB(lcomb(s1[ot][2], s2[ot][2]) * sc, lcomb(s1[ot][3], s2[ot][3]) * sc, h0, l0);
        dh[i0 + 128] = h0; dl[i0 + 128] = l0;
    }
}

// ============================================================================
// Kernel 2: FlashAttention, bf16 lambda-split (2 MMAs per GEMM term).
// 16q/warp, 64q/128thr CTA; 64-key tiles double-buffered; S in 32-key halves
// to cap register pressure; fixed-max softmax.
// ============================================================================
#define ROWB 80
#define ARRB (64 * ROWB)        // 5120
#define BUFB (4 * ARRB)         // 20480; 2 buffers = 40KB static

struct __align__(16) FSmem { unsigned char kv[2][4][ARRB]; };

__global__ __launch_bounds__(128) void fattn_kernel()
{
    __shared__ FSmem fs;
    unsigned sb = s2u(&fs);
    int tid = threadIdx.x;
    int lane = tid & 31, wid = tid >> 5;
    int qt = blockIdx.x, bh = blockIdx.y;
    int g = lane >> 2, tq = lane & 3;
    int lrow = lane & 7, lmi = lane >> 3;

    const uint4* srcs[4] = {
        g_khi + (size_t)bh * NTOK * 4, g_klo + (size_t)bh * NTOK * 4,
        g_vhi + (size_t)bh * NTOK * 4, g_vlo + (size_t)bh * NTOK * 4 };

    int c16 = tid & 3, r0 = tid >> 2;
    {
        #pragma unroll
        for (int i = 0; i < 8; i++) {
            int arr = i >> 1, row = (r0 + i * 32) & 63;
            unsigned dst = sb + arr * ARRB + row * ROWB + c16 * 16;
            CP_ASYNC(dst, srcs[arr] + (size_t)row * 4 + c16);
        }
        CP_COMMIT();
    }

    // ---- Q fragments (P0 / P1), 2 k-chunks ----
    unsigned q0[2][4], q1[2][4];
    {
        int qa = qt * 64 + wid * 16 + g;
        const unsigned* ph = (const unsigned*)(g_qhi + ((size_t)bh * NTOK + qa) * 4);
        const unsigned* pl = (const unsigned*)(g_qlo + ((size_t)bh * NTOK + qa) * 4);
        #pragma unroll
        for (int kb = 0; kb < 2; kb++) {
            q0[kb][0] = ph[8 * kb + tq];       q0[kb][2] = ph[8 * kb + 4 + tq];
            q0[kb][1] = ph[128 + 8 * kb + tq]; q0[kb][3] = ph[128 + 8 * kb + 4 + tq];
            q1[kb][0] = pl[8 * kb + tq];       q1[kb][2] = pl[8 * kb + 4 + tq];
            q1[kb][1] = pl[128 + 8 * kb + tq]; q1[kb][3] = pl[128 + 8 * kb + 4 + tq];
        }
    }

    float o1[4][4], o2[4][4];
    #pragma unroll
    for (int i = 0; i < 4; i++)
        #pragma unroll
        for (int j = 0; j < 4; j++) { o1[i][j] = 0.f; o2[i][j] = 0.f; }
    float l_a = 0.f, l_b = 0.f;

    int buf = 0;
    for (int kt = 0; kt < NTOK / 64; kt++) {
        if (kt < NTOK / 64 - 1) {
            unsigned bb = sb + (buf ^ 1) * BUFB;
            size_t goff = (size_t)(kt + 1) * 64 * 4;
            #pragma unroll
            for (int i = 0; i < 8; i++) {
                int arr = i >> 1, row = (r0 + i * 32) & 63;
                CP_ASYNC(bb + arr * ARRB + row * ROWB + c16 * 16,
                         srcs[arr] + goff + (size_t)row * 4 + c16);
            }
            CP_COMMIT();
            CP_WAIT(1);
        } else {
            CP_WAIT(0);
        }
        __syncthreads();

        unsigned kb_base = sb + buf * BUFB;
        unsigned vbase = kb_base + 2 * ARRB;

        #pragma unroll
        for (int h = 0; h < 2; h++) {           // 32-key halves
            // ---- S = lambda-combined Q.K^T : 4 MMAs per 8-key block ----
            float s1[4][4], s2[4][4];
            #pragma unroll
            for (int nb = 0; nb < 4; nb++)
                #pragma unroll
                for (int i = 0; i < 4; i++) { s1[nb][i] = 0.f; s2[nb][i] = 0.f; }

            #pragma unroll
            for (int nb = 0; nb < 4; nb++) {
                unsigned k00, k01, k02, k03, k10, k11, k12, k13;
                unsigned ka = kb_base + (h * 32 + 8 * nb + lrow) * ROWB + lmi * 16;
                LDSM_X4(k00, k01, k02, k03, ka);
                LDSM_X4(k10, k11, k12, k13, ka + ARRB);
                MMA_BF16(s1[nb], q0[0][0], q0[0][1], q0[0][2], q0[0][3], k00, k01);
                MMA_BF16(s1[nb], q0[1][0], q0[1][1], q0[1][2], q0[1][3], k02, k03);
                MMA_BF16(s2[nb], q1[0][0], q1[0][1], q1[0][2], q1[0][3], k10, k11);
                MMA_BF16(s2[nb], q1[1][0], q1[1][1], q1[1][2], q1[1][3], k12, k13);
            }

            // ---- combine + fixed-max softmax ----
            float sa = 0.f, sbm = 0.f;
            #pragma unroll
            for (int nb = 0; nb < 4; nb++) {
                s1[nb][0] = ex2f(lcomb(s1[nb][0], s2[nb][0]) - FIXMAX);
                s1[nb][1] = ex2f(lcomb(s1[nb][1], s2[nb][1]) - FIXMAX);
                s1[nb][2] = ex2f(lcomb(s1[nb][2], s2[nb][2]) - FIXMAX);
                s1[nb][3] = ex2f(lcomb(s1[nb][3], s2[nb][3]) - FIXMAX);
                sa  += s1[nb][0] + s1[nb][1];
                sbm += s1[nb][2] + s1[nb][3];
            }
            l_a += sa; l_b += sbm;

            // ---- O: o1 += P0.V0, o2 += P1.V1 (lambda split) ----
            #pragma unroll
            for (int kb = 0; kb < 2; kb++) {
                unsigned p0[4], p1[4];
                splitB(s1[2 * kb][0],     s1[2 * kb][1],     p0[0], p1[0]);
                splitB(s1[2 * kb][2],     s1[2 * kb][3],     p0[1], p1[1]);
                splitB(s1[2 * kb + 1][0], s1[2 * kb + 1][1], p0[2], p1[2]);
                splitB(s1[2 * kb + 1][2], s1[2 * kb + 1][3], p0[3], p1[3]);
                #pragma unroll
                for (int cp = 0; cp < 2; cp++) {
                    int oct = 2 * kb + (lmi & 1), chunk = 2 * cp + (lmi >> 1);
                    unsigned va = vbase + (h * 32 + oct * 8 + lrow) * ROWB + chunk * 16;
                    unsigned v00, v01, v02, v03, v10, v11, v12, v13;
                    LDSM_X4_T(v00, v01, v02, v03, va);
                    LDSM_X4_T(v10, v11, v12, v13, va + ARRB);
                    MMA_BF16(o1[2 * cp],     p0[0], p0[1], p0[2], p0[3], v00, v01);
                    MMA_BF16(o1[2 * cp + 1], p0[0], p0[1], p0[2], p0[3], v02, v03);
                    MMA_BF16(o2[2 * cp],     p1[0], p1[1], p1[2], p1[3], v10, v11);
                    MMA_BF16(o2[2 * cp + 1], p1[0], p1[1], p1[2], p1[3], v12, v13);
                }
            }
        }

        __syncthreads();
        buf ^= 1;
    }

    // ---- l reductions ----
    l_a += __shfl_xor_sync(0xffffffffu, l_a, 1);
    l_a += __shfl_xor_sync(0xffffffffu, l_a, 2);
    l_b += __shfl_xor_sync(0xffffffffu, l_b, 1);
    l_b += __shfl_xor_sync(0xffffffffu, l_b, 2);

    // ---- epilogue: lambda-combine O, normalize, split to P0/P1 ----
    float inv_a = 1.f / l_a, inv_b = 1.f / l_b;
    int b = bh >> 2, h = bh & 3;
    int qa = qt * 64 + wid * 16 + g;
    #pragma unroll
    for (int nb = 0; nb < 4; nb++) {
        int c = h * 32 + nb * 8 + 2 * tq;
        size_t i0 = ((size_t)b * NTOK + qa) * 64 + (c >> 1);
        unsigned hA, lA;
        splitB(lcomb(o1[nb][0], o2[nb][0]) * inv_a,
               lcomb(o1[nb][1], o2[nb][1]) * inv_a, hA, lA);
        g_ahi[i0] = hA; g_alo[i0] = lA;
        splitB(lcomb(o1[nb][2], o2[nb][2]) * inv_b,
               lcomb(o1[nb][3], o2[nb][3]) * inv_b, hA, lA);
        g_ahi[i0 + 8 * 64] = hA; g_alo[i0 + 8 * 64] = lA;
    }
}

// ============================================================================
// Kernel 3: output projection, bf16 lambda-split (4 MMAs per frag pair)
// ============================================================================
#define OROW 272
#define OARR 17408

__global__ __launch_bounds__(256) void out_mma(const float* __restrict__ bias,
                                               float* __restrict__ out)
{
    extern __shared__ unsigned char osm[];
    unsigned sb = s2u(osm);
    int tid = threadIdx.x, lane = tid & 31, wid = tid >> 5;
    int lrow = lane & 7, lmi = lane >> 3;
    int g = lane >> 2, tq = lane & 3;
    int n0 = blockIdx.x * 64, o0 = blockIdx.y * 64, b = blockIdx.z;

    #pragma unroll
    for (int i = tid; i < 4096; i += 256) {
        int arr = i >> 10, ch = i & 1023, r = ch >> 4, c16 = ch & 15;
        unsigned dst = sb + arr * OARR + r * OROW + c16 * 16;
        const char* src;
        if (arr < 2)
            src = (const char*)(arr ? g_wolo : g_wohi)
                + (((size_t)(o0 + r)) * 64 + c16 * 4) * 4;
        else
            src = (const char*)(arr == 2 ? g_ahi : g_alo)
                + (((size_t)(b * NTOK + n0 + r)) * 64 + c16 * 4) * 4;
        CP_ASYNC(dst, src);
    }
    CP_COMMIT(); CP_WAIT(0);
    __syncthreads();

    int ow = wid >> 1, nh = wid & 1;
    float s1[4][4], s2[4][4];
    #pragma unroll
    for (int i = 0; i < 4; i++)
        #pragma unroll
        for (int j = 0; j < 4; j++) { s1[i][j] = 0.f; s2[i][j] = 0.f; }

    unsigned abase = sb + (ow * 16 + (lane & 15)) * OROW + (lane >> 4) * 16;
    unsigned bbase = sb + 2 * OARR + (nh * 32 + lrow) * OROW + lmi * 16;

    #pragma unroll
    for (int ksl = 0; ksl < 4; ksl++) {
        unsigned ax00[4], ax01[4], ax10[4], ax11[4];
        LDSM_X4(ax00[0], ax00[1], ax00[2], ax00[3], abase + ksl * 64);
        LDSM_X4(ax01[0], ax01[1], ax01[2], ax01[3], abase + ksl * 64 + 32);
        LDSM_X4(ax10[0], ax10[1], ax10[2], ax10[3], abase + OARR + ksl * 64);
        LDSM_X4(ax11[0], ax11[1], ax11[2], ax11[3], abase + OARR + ksl * 64 + 32);
        #pragma unroll
        for (int nt = 0; nt < 4; nt++) {
            unsigned bh0, bh1, bh2, bh3, bl0, bl1, bl2, bl3;
            unsigned ba = bbase + nt * (8 * OROW) + ksl * 64;
            LDSM_X4(bh0, bh1, bh2, bh3, ba);
            LDSM_X4(bl0, bl1, bl2, bl3, ba + OARR);
            MMA_BF16(s1[nt], ax00[0], ax00[1], ax00[2], ax00[3], bh0, bh1);
            MMA_BF16(s1[nt], ax01[0], ax01[1], ax01[2], ax01[3], bh2, bh3);
            MMA_BF16(s2[nt], ax10[0], ax10[1], ax10[2], ax10[3], bl0, bl1);
            MMA_BF16(s2[nt], ax11[0], ax11[1], ax11[2], ax11[3], bl2, bl3);
        }
    }

    int o = o0 + ow * 16 + g;
    float b0 = bias[o], b1 = bias[o + 8];
    #pragma unroll
    for (int nt = 0; nt < 4; nt++) {
        int n = n0 + nh * 32 + nt * 8 + 2 * tq;
        *(float2*)&out[((size_t)(b * CIN + o)) * NTOK + n] =
            make_float2(lcomb(s1[nt][0], s2[nt][0]) + b0,
                        lcomb(s1[nt][1], s2[nt][1]) + b0);
        *(float2*)&out[((size_t)(b * CIN + o + 8)) * NTOK + n] =
            make_float2(lcomb(s1[nt][2], s2[nt][2]) + b1,
                        lcomb(s1[nt][3], s2[nt][3]) + b1);
    }
}

// ============================================================================
extern "C" void kernel_launch(void* const* d_in, const int* in_sizes, int n_in,
                              void* d_out, int out_size)
{
    (void)in_sizes; (void)n_in; (void)out_size;
    const float* x     = (const float*)d_in[0];
    const float* w_qkv = (const float*)d_in[1];
    const float* w_out = (const float*)d_in[2];
    const float* b_out = (const float*)d_in[3];
    float* out = (float*)d_out;

    cudaFuncSetAttribute(qkv_mma, cudaFuncAttributeMaxDynamicSharedMemorySize, 2 * QBUF);
    cudaFuncSetAttribute(out_mma, cudaFuncAttributeMaxDynamicSharedMemorySize, 4 * OARR);

    int total = NX2 + NWQ2 + NWO2;
    split_kernel<<<(total + 255) / 256, 256>>>(x, w_qkv, w_out);
    qkv_mma<<<dim3(32, 6, 4), 256, 2 * QBUF>>>();
    fattn_kernel<<<dim3(NTOK / 64, BH), 128>>>();
    out_mma<<<dim3(64, 4, 4), 256, 4 * OARR>>>(b_out, out);
}